// round 9
// baseline (speedup 1.0000x reference)
#include <cuda_runtime.h>
#include <cstdint>

#define TSTEPS 60
#define NG 8192                 // 32768 batches / 4 per group
#define PSTRIDE 1010            // 72*14 + 2 pad u64 (keeps parts bank-dephased)
typedef unsigned long long u64;

__device__ __forceinline__ u64 pk(float a, float b) {
    u64 r; asm("mov.b64 %0, {%1, %2};" : "=l"(r) : "f"(a), "f"(b)); return r;
}
__device__ __forceinline__ void upk(u64 v, float& a, float& b) {
    asm("mov.b64 {%0, %1}, %2;" : "=f"(a), "=f"(b) : "l"(v));
}
__device__ __forceinline__ float lof(u64 v) { float a, b; upk(v, a, b); return a; }
__device__ __forceinline__ float hif(u64 v) { float a, b; upk(v, a, b); return b; }
__device__ __forceinline__ void ffma2_ip(u64& acc, u64 a, u64 b) {
    asm("fma.rn.f32x2 %0, %1, %2, %0;" : "+l"(acc) : "l"(a), "l"(b));
}
__device__ __forceinline__ float hadd(u64 v) { float a, b; upk(v, a, b); return a + b; }
__device__ __forceinline__ float sigmoidf_(float x) {
    return __fdividef(1.0f, 1.0f + __expf(-x));
}
__device__ __forceinline__ float tanhf_(float x) {
    return __fdividef(2.0f, 1.0f + __expf(-2.0f * x)) - 1.0f;
}

// Weight table s_w[part][row 0..71][14 k-pair u64].
//  part0 (h-side): j<12 = w_hh pairs; j==12 = (b_hh,0) for n-rows only; j==13 = 0
//  part1 (x-side): j<13 = w_ih pairs; j==13 = (b_ih+b_hh,0) for r/z rows, (b_ih,0) for n rows
// Matching activation pads: h-side act[12]=pk(1,0), x-side act[13]=pk(1,0).

__global__ void __launch_bounds__(224, 1)
_ShotRNN_90417651516362_kernel(
    const float* __restrict__ x, const float* __restrict__ w_ih,
    const float* __restrict__ w_hh, const float* __restrict__ b_ih,
    const float* __restrict__ b_hh, const float* __restrict__ fc1_w,
    const float* __restrict__ fc1_b, const float* __restrict__ fc2_w,
    const float* __restrict__ fc2_b, float* __restrict__ out)
{
    __shared__ __align__(16) u64 s_w[2 * PSTRIDE];
    __shared__ float s_fc[236];

    const int tid = threadIdx.x;
    for (int idx = tid; idx < 2 * 72 * 14; idx += 224) {
        int p = idx / (72 * 14), rem = idx - p * (72 * 14);
        int r2 = rem / 14, j = rem % 14;
        float a = 0.0f, b = 0.0f;
        if (p == 0) {
            if (j < 12) { a = w_hh[r2 * 24 + 2 * j]; b = w_hh[r2 * 24 + 2 * j + 1]; }
            else if (j == 12 && r2 >= 48) a = b_hh[r2];
        } else {
            if (j < 13) { a = w_ih[r2 * 26 + 2 * j]; b = w_ih[r2 * 26 + 2 * j + 1]; }
            else if (j == 13) a = (r2 < 48) ? (b_ih[r2] + b_hh[r2]) : b_ih[r2];
        }
        s_w[p * PSTRIDE + r2 * 14 + j] = pk(a, b);
    }
    for (int i = tid; i < 192; i += 224) s_fc[i] = fc1_w[i];
    if (tid < 8)  s_fc[192 + tid] = fc1_b[tid];
    if (tid < 32) s_fc[200 + tid] = fc2_w[tid];
    if (tid < 4)  s_fc[232 + tid] = fc2_b[tid];
    __syncthreads();

    const int lane = tid & 31;
    const int part = lane & 1;            // 0 = h-side, 1 = x-side
    const int rh   = (lane >> 1) & 1;     // 0 = units 0-11, 1 = units 12-23
    int grp = (blockIdx.x * 7 + (tid >> 5)) * 8 + (lane >> 2);
    if (grp >= NG) grp = NG - 1;          // tail clamp: duplicate identical work
    const u64* wbase = s_w + part * PSTRIDE;
    const int ubase = rh * 12;

    // act[b][j]: h-side: j<12 pk(h[2j],h[2j+1]), [12]=pk(1,0), [13]=0
    //            x-side: j<13 pk(x[2j],x[2j+1]), [13]=pk(1,0)
    u64 act[4][14];
    if (part == 0) {
#pragma unroll
        for (int b = 0; b < 4; b++) {
#pragma unroll
            for (int j = 0; j < 12; j++) act[b][j] = 0ull;
            act[b][12] = pk(1.0f, 0.0f);
            act[b][13] = 0ull;
        }
    } else {
#pragma unroll
        for (int b = 0; b < 4; b++) {
            const u64* px = (const u64*)(x + (size_t)(grp * 4 + b) * 1560);
#pragma unroll
            for (int j = 0; j < 13; j++) act[b][j] = __ldg(px + j);
            act[b][13] = pk(1.0f, 0.0f);
        }
    }

#pragma unroll 1
    for (int t = 0; t < TSTEPS; t++) {
        u64 outp[12];   // new h for my 12 units, packed over my 2 batches

#pragma unroll
        for (int i = 0; i < 12; i++) {
            const int u = ubase + i;
            const ulonglong2* w0 = (const ulonglong2*)(wbase + u * 14);
            const ulonglong2* w1 = (const ulonglong2*)(wbase + (24 + u) * 14);
            const ulonglong2* w2 = (const ulonglong2*)(wbase + (48 + u) * 14);

            u64 a0[4] = {0,0,0,0}, a1[4] = {0,0,0,0}, a2[4] = {0,0,0,0};
#pragma unroll
            for (int jj = 0; jj < 7; jj++) {
                ulonglong2 W0 = w0[jj], W1 = w1[jj], W2 = w2[jj];
#pragma unroll
                for (int b = 0; b < 4; b++) {
                    ffma2_ip(a0[b], act[b][2*jj],   W0.x);
                    ffma2_ip(a1[b], act[b][2*jj],   W1.x);
                    ffma2_ip(a2[b], act[b][2*jj],   W2.x);
                    ffma2_ip(a0[b], act[b][2*jj+1], W0.y);
                    ffma2_ip(a1[b], act[b][2*jj+1], W1.y);
                    ffma2_ip(a2[b], act[b][2*jj+1], W2.y);
                }
            }
            float s0[4], s1[4], s2[4];
#pragma unroll
            for (int b = 0; b < 4; b++) {
                s0[b] = hadd(a0[b]); s1[b] = hadd(a1[b]); s2[b] = hadd(a2[b]);
            }

            // exchange: each lane keeps its 2 epilogue batches
            // part0 -> batches 0,1 ; part1 -> batches 2,3
            u64 t0 = part ? pk(s0[0], s0[1]) : pk(s0[2], s0[3]);
            u64 t1 = part ? pk(s1[0], s1[1]) : pk(s1[2], s1[3]);
            u64 t2 = part ? pk(s2[0], s2[1]) : pk(s2[2], s2[3]);
            // h_old transfer: h-side sends its act h for batches 2,3
            const int jh = (rh * 6) + (i >> 1);
            float ha0, ha1, hb0, hb1;
            if (part == 0) {
                ha0 = (u & 1) ? hif(act[0][jh]) : lof(act[0][jh]);
                ha1 = (u & 1) ? hif(act[1][jh]) : lof(act[1][jh]);
                hb0 = (u & 1) ? hif(act[2][jh]) : lof(act[2][jh]);
                hb1 = (u & 1) ? hif(act[3][jh]) : lof(act[3][jh]);
            } else { ha0 = ha1 = hb0 = hb1 = 0.0f; }
            u64 th = pk(hb0, hb1);
            u64 r0 = __shfl_xor_sync(0xffffffffu, t0, 1);
            u64 r1 = __shfl_xor_sync(0xffffffffu, t1, 1);
            u64 r2 = __shfl_xor_sync(0xffffffffu, t2, 1);
            u64 rhh = __shfl_xor_sync(0xffffffffu, th, 1);

            // my partials (2 batches) + partner partials
            float m0a = part ? s0[2] : s0[0], m0b = part ? s0[3] : s0[1];
            float m1a = part ? s1[2] : s1[0], m1b = part ? s1[3] : s1[1];
            float m2a = part ? s2[2] : s2[0], m2b = part ? s2[3] : s2[1];
            float o0a = lof(r0), o0b = hif(r0);
            float o1a = lof(r1), o1b = hif(r1);
            float o2a = lof(r2), o2b = hif(r2);
            float hoa = part ? lof(rhh) : ha0;
            float hob = part ? hif(rhh) : ha1;

            float rra = sigmoidf_(m0a + o0a), rrb = sigmoidf_(m0b + o0b);
            float zza = sigmoidf_(m1a + o1a), zzb = sigmoidf_(m1b + o1b);
            // n = tanh(xn + r*hn): identify parts
            float hna = part ? o2a : m2a, xna = part ? m2a : o2a;
            float hnb = part ? o2b : m2b, xnb = part ? m2b : o2b;
            float nna = tanhf_(fmaf(rra, hna, xna));
            float nnb = tanhf_(fmaf(rrb, hnb, xnb));
            float hA = fmaf(zza, hoa - nna, nna);
            float hB = fmaf(zzb, hob - nnb, nnb);
            outp[i] = pk(hA, hB);
        }

        // ---- gather: rebuild h-side act from the 4 roles (chunked shfl) ----
#pragma unroll
        for (int c = 0; c < 6; c++) {
            u64 oa = outp[2*c], ob = outp[2*c+1];
            u64 g1a = __shfl_xor_sync(0xffffffffu, oa, 1);
            u64 g1b = __shfl_xor_sync(0xffffffffu, ob, 1);
            u64 g2a = __shfl_xor_sync(0xffffffffu, oa, 2);
            u64 g2b = __shfl_xor_sync(0xffffffffu, ob, 2);
            u64 g3a = __shfl_xor_sync(0xffffffffu, oa, 3);
            u64 g3b = __shfl_xor_sync(0xffffffffu, ob, 3);
            if (part == 0) {
                const int jm = rh * 6 + c;          // my region's act index
                const int jo = (1 - rh) * 6 + c;    // other region's act index
                act[0][jm] = pk(lof(oa),  lof(ob));
                act[1][jm] = pk(hif(oa),  hif(ob));
                act[2][jm] = pk(lof(g1a), lof(g1b));
                act[3][jm] = pk(hif(g1a), hif(g1b));
                act[0][jo] = pk(lof(g2a), lof(g2b));
                act[1][jo] = pk(hif(g2a), hif(g2b));
                act[2][jo] = pk(lof(g3a), lof(g3b));
                act[3][jo] = pk(hif(g3a), hif(g3b));
            }
        }

        // ---- x-side: load x(t+1) ----
        if (part == 1 && t + 1 < TSTEPS) {
#pragma unroll
            for (int b = 0; b < 4; b++) {
                const u64* px = (const u64*)(x + (size_t)(grp * 4 + b) * 1560
                                             + (size_t)(t + 1) * 26);
#pragma unroll
                for (int j = 0; j < 13; j++) act[b][j] = __ldg(px + j);
            }
        }
    }

    // ---- FC head: h-side lanes; rh selects the batch pair ----
    if (part == 0) {
#pragma unroll
        for (int m = 0; m < 2; m++) {
            const int bsel = rh * 2 + m;
            float hv[24];
#pragma unroll
            for (int j = 0; j < 12; j++) { hv[2*j] = lof(act[bsel][j]); hv[2*j+1] = hif(act[bsel][j]); }
            float f1[8];
#pragma unroll
            for (int jy = 0; jy < 8; jy++) {
                float a = s_fc[192 + jy];
#pragma unroll
                for (int k = 0; k < 24; k++) a = fmaf(hv[k], s_fc[jy * 24 + k], a);
                f1[jy] = fmaxf(a, 0.0f);
            }
            float l[4];
#pragma unroll
            for (int c = 0; c < 4; c++) {
                float a = s_fc[232 + c];
#pragma unroll
                for (int k = 0; k < 8; k++) a = fmaf(f1[k], s_fc[200 + c * 8 + k], a);
                l[c] = a;
            }
            float mx = fmaxf(fmaxf(l[0], l[1]), fmaxf(l[2], l[3]));
            float e0 = __expf(l[0]-mx), e1 = __expf(l[1]-mx);
            float e2 = __expf(l[2]-mx), e3 = __expf(l[3]-mx);
            float inv = __fdividef(1.0f, e0 + e1 + e2 + e3);
            *(float4*)(out + (size_t)(grp * 4 + bsel) * 4) =
                make_float4(e0 * inv, e1 * inv, e2 * inv, e3 * inv);
        }
    }
}

extern "C" void kernel_launch(void* const* d_in, const int* in_sizes, int n_in,
                              void* d_out, int out_size) {
    // 147 CTAs x 224 threads; 4-lane groups own 4 batches (h/x x rowhalf split)
    _ShotRNN_90417651516362_kernel<<<147, 224>>>(
        (const float*)d_in[0], (const float*)d_in[1], (const float*)d_in[2],
        (const float*)d_in[3], (const float*)d_in[4], (const float*)d_in[5],
        (const float*)d_in[6], (const float*)d_in[7], (const float*)d_in[8],
        (float*)d_out);
}